// round 12
// baseline (speedup 1.0000x reference)
#include <cuda_runtime.h>
#include <cuda_fp16.h>
#include <cstdint>
#include <cstddef>

#define NB   32
#define HWD  56
#define CIN  128
#define OC   256
#define NTILE 25088                 // 32 * 28 * 28 output 2x2 tiles
#define NTK  ((size_t)NTILE * 128)  // elements per position plane of U

// scratch (no runtime allocation allowed)
__device__ __align__(16) __half g_u[(size_t)16 * NTILE * 128]; // U[pos][tile*128+c]
__device__ __align__(16) __half g_v[(size_t)16 * OC * 128];    // V[pos][oc*128+c]

__device__ __forceinline__ uint32_t smem_u32(const void* p) {
    uint32_t a;
    asm("{ .reg .u64 t; cvta.to.shared.u64 t, %1; cvt.u32.u64 %0, t; }"
        : "=r"(a) : "l"(p));
    return a;
}
#define CPA16(dst, src) \
    asm volatile("cp.async.cg.shared.global [%0], [%1], 16;" \
                 :: "r"(dst), "l"(src))
#define CPA_COMMIT() asm volatile("cp.async.commit_group;")

__device__ __forceinline__ void ldsm4(uint32_t& r0, uint32_t& r1, uint32_t& r2,
                                      uint32_t& r3, uint32_t addr) {
    asm volatile("ldmatrix.sync.aligned.m8n8.x4.shared.b16 {%0,%1,%2,%3}, [%4];"
                 : "=r"(r0), "=r"(r1), "=r"(r2), "=r"(r3) : "r"(addr));
}

// ---------------------------------------------------------------------------
// Weight transform: V = G g G^T per (oc, c). Exact multiples of 1/4, |V|<512.
// ---------------------------------------------------------------------------
__global__ void wino_wv(const float* __restrict__ wt) {
    int t = blockIdx.x * 256 + threadIdx.x;   // 32768 = 256 oc * 128 c
    if (t >= OC * CIN) return;
    const float* gp = wt + (size_t)t * 9;
    float g[3][3];
#pragma unroll
    for (int r = 0; r < 3; r++)
#pragma unroll
        for (int s = 0; s < 3; s++)
            g[r][s] = (float)(int)gp[r * 3 + s];   // trunc == jnp.trunc

    float tw[4][3];
#pragma unroll
    for (int s = 0; s < 3; s++) {
        tw[0][s] = g[0][s];
        tw[1][s] = 0.5f * (g[0][s] + g[1][s] + g[2][s]);
        tw[2][s] = 0.5f * (g[0][s] - g[1][s] + g[2][s]);
        tw[3][s] = g[2][s];
    }
#pragma unroll
    for (int i = 0; i < 4; i++) {
        float v0 = tw[i][0];
        float v1 = 0.5f * (tw[i][0] + tw[i][1] + tw[i][2]);
        float v2 = 0.5f * (tw[i][0] - tw[i][1] + tw[i][2]);
        float v3 = tw[i][2];
        g_v[(size_t)(i * 4 + 0) * (OC * 128) + t] = __float2half_rn(v0);
        g_v[(size_t)(i * 4 + 1) * (OC * 128) + t] = __float2half_rn(v1);
        g_v[(size_t)(i * 4 + 2) * (OC * 128) + t] = __float2half_rn(v2);
        g_v[(size_t)(i * 4 + 3) * (OC * 128) + t] = __float2half_rn(v3);
    }
}

// ---------------------------------------------------------------------------
// Input transform: U = B^T d B per (tile, c). Integers |U| <= 508, exact fp16.
// One block per (n, ty): loads 128ch x 4row x 56col patch strip as int8.
// ---------------------------------------------------------------------------
__global__ void wino_in(const float* __restrict__ x) {
    __shared__ signed char d8[128 * 228];   // [c]: pitch 228 = 4 rows * 57
    const int tid = threadIdx.x;
    const int n = blockIdx.x / 28, ty = blockIdx.x - n * 28;
    const int gy0 = 2 * ty - 1;

    for (int i = tid; i < 128 * 4 * 56; i += 256) {
        int c = i / 224, r2 = i - c * 224;
        int rr = r2 / 56, xx = r2 - rr * 56;
        int gy = gy0 + rr;
        float v = ((unsigned)gy < 56u)
                  ? x[(((size_t)n * CIN + c) * 56 + gy) * 56 + xx] : 0.0f;
        d8[c * 228 + rr * 57 + xx] = (signed char)(int)v;  // trunc
    }
    __syncthreads();

    for (int it = tid; it < 28 * 128; it += 256) {
        int tx = it >> 7, c = it & 127;
        int x0 = 2 * tx - 1;
        int d[4][4];
#pragma unroll
        for (int r = 0; r < 4; r++)
#pragma unroll
            for (int s = 0; s < 4; s++) {
                int gx = x0 + s;
                d[r][s] = ((unsigned)gx < 56u) ? (int)d8[c * 228 + r * 57 + gx] : 0;
            }
        int td[4][4];
#pragma unroll
        for (int s = 0; s < 4; s++) {
            td[0][s] = d[0][s] - d[2][s];
            td[1][s] = d[1][s] + d[2][s];
            td[2][s] = d[2][s] - d[1][s];
            td[3][s] = d[1][s] - d[3][s];
        }
        int tile = (n * 28 + ty) * 28 + tx;
        __half* up = g_u + (size_t)tile * 128 + c;
#pragma unroll
        for (int i = 0; i < 4; i++) {
            int u0 = td[i][0] - td[i][2];
            int u1 = td[i][1] + td[i][2];
            int u2 = td[i][2] - td[i][1];
            int u3 = td[i][1] - td[i][3];
            up[(size_t)(i * 4 + 0) * NTK] = __float2half_rn((float)u0);
            up[(size_t)(i * 4 + 1) * NTK] = __float2half_rn((float)u1);
            up[(size_t)(i * 4 + 2) * NTK] = __float2half_rn((float)u2);
            up[(size_t)(i * 4 + 3) * NTK] = __float2half_rn((float)u3);
        }
    }
}

// ---------------------------------------------------------------------------
// Winograd GEMM: 16 positions, CTA = 32 tiles x 64 oc, K=128 as 8 k16 stages.
// 512 threads = 16 warps; warp w computes position w (M32 x N64 x K128).
// 2-buffer cp.async (96KB) -> 2 CTAs/SM = 8 warps/SMSP; trailing sync closes
// the WAR hazard. Fused output transform + requant epilogue.
// ---------------------------------------------------------------------------
#define A_SZ   16384                 // 16 pos * 32 tiles * 32B
#define B_SZ   32768                 // 16 pos * 64 oc * 32B
#define STG_SZ (A_SZ + B_SZ)         // 49152
#define SMEM_TOTAL (2 * STG_SZ)      // 98304
#define EPITCH 68                    // epilogue smem floats per tile row

__global__ void __launch_bounds__(512, 2) wino_gemm(
    const float* __restrict__ bias, const int* __restrict__ Aq,
    const int* __restrict__ Nq, const int* __restrict__ pmin,
    const int* __restrict__ pmax, float* __restrict__ out)
{
    extern __shared__ __align__(128) char smem[];
    const uint32_t sb = smem_u32(smem);

    const int tid  = threadIdx.x;
    const int lane = tid & 31, wid = tid >> 5;          // wid == position
    const int gid  = lane >> 2, tg = lane & 3;
    const int lrow = lane & 15, lhi = lane >> 4;
    const int oc0   = blockIdx.x * 64;
    const int tile0 = blockIdx.y * 32;

    // ---- loader mapping: 3072 x 16B chunks per stage, 6 per thread ----
    // j = 0,1 -> A chunks (g_u); j = 2..5 -> B chunks (g_v). Offsets in halves.
    uint32_t dsto[6], goff[6];
#pragma unroll
    for (int j = 0; j < 6; j++) {
        int cid = j * 512 + tid;
        if (cid < 1024) {            // A: id = pos*64 + tile*2 + kh
            int pos = cid >> 6, rem = cid & 63;
            int tl = rem >> 1, kh = rem & 1;
            dsto[j] = (uint32_t)(pos * 1024 + kh * 512 + tl * 16);
            goff[j] = (uint32_t)(pos * NTK + (size_t)(tile0 + tl) * 128 + kh * 8);
        } else {                     // B: id = pos*128 + oc*2 + kh
            int c2 = cid - 1024;
            int pos = c2 >> 7, rem = c2 & 127;
            int oc = rem >> 1, kh = rem & 1;
            dsto[j] = (uint32_t)(A_SZ + pos * 2048 + kh * 1024 + oc * 16);
            goff[j] = (uint32_t)(pos * (OC * 128) + (oc0 + oc) * 128 + kh * 8);
        }
    }
    auto load_stage = [&](int buf, int ks) {
        const uint32_t d0 = sb + buf * STG_SZ;
#pragma unroll
        for (int j = 0; j < 2; j++)
            CPA16(d0 + dsto[j], g_u + goff[j] + ks * 16);
#pragma unroll
        for (int j = 2; j < 6; j++)
            CPA16(d0 + dsto[j], g_v + goff[j] + ks * 16);
    };

    float acc[2][8][4];
#pragma unroll
    for (int a = 0; a < 2; a++)
#pragma unroll
        for (int b = 0; b < 8; b++)
#pragma unroll
            for (int c = 0; c < 4; c++) acc[a][b][c] = 0.0f;

    load_stage(0, 0); CPA_COMMIT();

    for (int ks = 0; ks < 8; ks++) {
        const int buf = ks & 1;
        if (ks + 1 < 8) load_stage(buf ^ 1, ks + 1);
        CPA_COMMIT();
        asm volatile("cp.async.wait_group 1;");
        __syncthreads();

        const uint32_t Ab = sb + buf * STG_SZ + wid * 1024;
        const uint32_t Bb = sb + buf * STG_SZ + A_SZ + wid * 2048;

        uint32_t bf[8][2];
#pragma unroll
        for (int bt = 0; bt < 4; bt++) {
            uint32_t addr = Bb + (uint32_t)lhi * 1024 + (uint32_t)(bt * 16 + lrow) * 16;
            ldsm4(bf[bt * 2][0], bf[bt * 2 + 1][0],
                  bf[bt * 2][1], bf[bt * 2 + 1][1], addr);
        }
#pragma unroll
        for (int mt = 0; mt < 2; mt++) {
            uint32_t addr = Ab + (uint32_t)lhi * 512 + (uint32_t)(mt * 16 + lrow) * 16;
            uint32_t a0, a1, a2, a3;
            ldsm4(a0, a1, a2, a3, addr);
#pragma unroll
            for (int nt = 0; nt < 8; nt++) {
                asm volatile(
                    "mma.sync.aligned.m16n8k16.row.col.f32.f16.f16.f32 "
                    "{%0,%1,%2,%3}, {%4,%5,%6,%7}, {%8,%9}, {%0,%1,%2,%3};\n"
                    : "+f"(acc[mt][nt][0]), "+f"(acc[mt][nt][1]),
                      "+f"(acc[mt][nt][2]), "+f"(acc[mt][nt][3])
                    : "r"(a0), "r"(a1), "r"(a2), "r"(a3),
                      "r"(bf[nt][0]), "r"(bf[nt][1]));
            }
        }
        __syncthreads();   // close WAR hazard before next iteration's cp.async
    }

    // ---- epilogue: inverse transform A^T M A + bias + requant + clip ----
    const int omin = *pmin, omax = *pmax;
    const float fmin = (float)omin, fmax = (float)omax;
    float* smf = (float*)smem;      // [pos][tile16 * EPITCH + oc64], 69632 B

    for (int chunk = 0; chunk < 2; chunk++) {
        __syncthreads();
        // scatter this chunk's accumulators: tiles chunk*16 .. +15
#pragma unroll
        for (int nt = 0; nt < 8; nt++)
#pragma unroll
            for (int q = 0; q < 4; q++) {
                int tl = gid + 8 * (q >> 1);
                int oc = nt * 8 + tg * 2 + (q & 1);
                smf[wid * (16 * EPITCH) + tl * EPITCH + oc] = acc[chunk][nt][q];
            }
        __syncthreads();

#pragma unroll
        for (int ii = 0; ii < 2; ii++) {
            int item = ii * 512 + tid;          // 1024 = 64 oc * 16 tiles
            int oc_l = item >> 4, tl = item & 15;
            int Tg = tile0 + chunk * 16 + tl;
            int n = Tg / 784, r = Tg - n * 784;
            int tyy = r / 28, txx = r - tyy * 28;
            int oc = oc0 + oc_l;

            float m[16];
#pragma unroll
            for (int p = 0; p < 16; p++)
                m[p] = smf[p * (16 * EPITCH) + tl * EPITCH + oc_l];

            float tm0[4], tm1[4];
#pragma unroll
            for (int v = 0; v < 4; v++) {
                tm0[v] = m[v] + m[4 + v] + m[8 + v];
                tm1[v] = m[4 + v] - m[8 + v] - m[12 + v];
            }
            float Y00 = tm0[0] + tm0[1] + tm0[2];
            float Y01 = tm0[1] - tm0[2] - tm0[3];
            float Y10 = tm1[0] + tm1[1] + tm1[2];
            float Y11 = tm1[1] - tm1[2] - tm1[3];

            float bv = __ldg(&bias[oc]);
            float sc = ldexpf((float)__ldg(&Aq[oc]), -__ldg(&Nq[oc]));
            float f00 = (Y00 + bv) * sc, f01 = (Y01 + bv) * sc;
            float f10 = (Y10 + bv) * sc, f11 = (Y11 + bv) * sc;
            if (omin >= 0) {
                f00 = fminf(fmaxf(rintf(f00), fmin), fmax);
                f01 = fminf(fmaxf(rintf(f01), fmin), fmax);
                f10 = fminf(fmaxf(rintf(f10), fmin), fmax);
                f11 = fminf(fmaxf(rintf(f11), fmin), fmax);
            }
            float* ob = out + (((size_t)n * OC + oc) * 56 + 2 * tyy) * 56 + 2 * txx;
            ob[0] = f00; ob[1] = f01;
            ob[56] = f10; ob[57] = f11;
        }
    }
}

// ---------------------------------------------------------------------------
// Launch. Inputs: x, weight_int, bias_int, A, N, out_min, out_max
// ---------------------------------------------------------------------------
extern "C" void kernel_launch(void* const* d_in, const int* in_sizes, int n_in,
                              void* d_out, int out_size) {
    const float* x    = (const float*)d_in[0];
    const float* wt   = (const float*)d_in[1];
    const float* bias = (const float*)d_in[2];
    const int*   Aq   = (const int*)d_in[3];
    const int*   Nq   = (const int*)d_in[4];
    const int*   omin = (const int*)d_in[5];
    const int*   omax = (const int*)d_in[6];
    float* out = (float*)d_out;

    static int configured = 0;
    if (!configured) {
        cudaFuncSetAttribute(wino_gemm, cudaFuncAttributeMaxDynamicSharedMemorySize,
                             SMEM_TOTAL);
        configured = 1;
    }

    wino_wv<<<(OC * CIN + 255) / 256, 256>>>(wt);
    wino_in<<<NB * 28, 256>>>(x);
    dim3 grid(OC / 64, NTILE / 32);   // oc-split inner => U reuse in L2
    wino_gemm<<<grid, 512, SMEM_TOTAL>>>(bias, Aq, Nq, omin, omax, out);
}

// round 13
// speedup vs baseline: 3.6222x; 3.6222x over previous
#include <cuda_runtime.h>
#include <cuda_fp16.h>
#include <cstdint>
#include <cstddef>

#define NB   32
#define HWD  56
#define CIN  128
#define OC   256
#define NPIX (NB*HWD*HWD)   // 100352
#define KW   1152           // 9*128

// scratch (no runtime allocation allowed)
__device__ __align__(16) __half g_x16[(size_t)NPIX * CIN]; // NHWC fp16 (exact ints)
__device__ __align__(16) __half g_w16[(size_t)OC * KW];    // [oc][(r*3+s)*128+c]

__device__ __forceinline__ uint32_t smem_u32(const void* p) {
    uint32_t a;
    asm("{ .reg .u64 t; cvta.to.shared.u64 t, %1; cvt.u32.u64 %0, t; }"
        : "=r"(a) : "l"(p));
    return a;
}
#define CPA16(dst, src, sz) \
    asm volatile("cp.async.cg.shared.global [%0], [%1], 16, %2;" \
                 :: "r"(dst), "l"(src), "r"(sz))
#define CPA_COMMIT() asm volatile("cp.async.commit_group;")

__device__ __forceinline__ void ldsm4(uint32_t& r0, uint32_t& r1, uint32_t& r2,
                                      uint32_t& r3, uint32_t addr) {
    asm volatile("ldmatrix.sync.aligned.m8n8.x4.shared.b16 {%0,%1,%2,%3}, [%4];"
                 : "=r"(r0), "=r"(r1), "=r"(r2), "=r"(r3) : "r"(addr));
}

// ---------------------------------------------------------------------------
// Fused prep: blocks [0, 1792) convert x (fp32 NCHW -> fp16 NHWC, one block
// per (n,h) plane); blocks [1792, 2944) convert weights (OIHW -> [oc][rs*128+c]).
// ---------------------------------------------------------------------------
#define XBLKS (NB * HWD)                       // 1792
#define WBLKS ((OC * KW) / 256)                // 1152

__global__ void prep_fused(const float* __restrict__ x,
                           const float* __restrict__ wt) {
    const int tid = threadIdx.x;

    if (blockIdx.x >= XBLKS) {
        // ---- weight transform ----
        int i = (blockIdx.x - XBLKS) * 256 + tid;
        int oc = i / KW, k = i - oc * KW;
        int rs = k >> 7, c = k & 127;
        int r = rs / 3, s = rs - r * 3;
        float v = wt[(((size_t)oc * CIN + c) * 3 + r) * 3 + s];
        g_w16[i] = __float2half_rn((float)(int)v);
        return;
    }

    // ---- activation transform ----
    __shared__ __half t[56 * 132];
    int n = blockIdx.x / 56, h = blockIdx.x - n * 56;
    const float* src = x + (size_t)n * CIN * 3136 + h * 56;

    int c = tid / 56, w = tid - c * 56;
#pragma unroll
    for (int i = 0; i < 28; i++) {
        float v = src[(size_t)c * 3136 + w];
        t[w * 132 + c] = __float2half_rn((float)(int)v);  // trunc == jnp.trunc, exact
        w += 32; c += 4;
        if (w >= 56) { w -= 56; c += 1; }
    }
    __syncthreads();

    uint2* go = (uint2*)(g_x16 + (size_t)blockIdx.x * 56 * 128);
#pragma unroll
    for (int i = 0; i < 7; i++) {
        int widx = i * 256 + tid;
        int ww = widx >> 5, c4 = widx & 31;
        go[widx] = *(const uint2*)&t[ww * 132 + c4 * 4];
    }
}

// ---------------------------------------------------------------------------
// Main kernel: implicit GEMM via mma.sync m16n8k16 f16 (f32 accum).
// CTA tile 128 pix x 128 oc; 512 threads, 16 warps = 4(M) x 4(N),
// warp tile 32 x 32 (acc = 32 regs/thread -> no spills).
// K = 18 stages of 64 channels; 3-buffer cp.async, 96KB smem,
// 2 CTAs/SM = 8 warps/SMSP.
// ---------------------------------------------------------------------------
#define ASZ    16384                // 128 rows x 128 B (64 halves)
#define STG_SZ 32768                // A + B
#define SMEM_TOTAL (3 * STG_SZ)     // 98304

__global__ void __launch_bounds__(512, 2) qconv(
    const float* __restrict__ bias, const int* __restrict__ Aq,
    const int* __restrict__ Nq, const int* __restrict__ pmin,
    const int* __restrict__ pmax, float* __restrict__ out)
{
    extern __shared__ __align__(128) signed char smem[];
    const uint32_t sb = smem_u32(smem);

    const int tid  = threadIdx.x;
    const int lane = tid & 31, wid = tid >> 5;
    const int gid  = lane >> 2, tg = lane & 3;
    const int warp_m = wid >> 2, warp_n = wid & 3;       // 4 x 4
    const int p0  = blockIdx.x * 128;
    const int oc0 = blockIdx.y * 128;

    // loader: 512 threads, thread -> (row = tid>>2, q = tid&3), 2 chunks each op
    const int row = tid >> 2, q = tid & 3;
    const int p = p0 + row;
    const int n = p / 3136, rem = p - n * 3136;
    const int h = rem / 56, w = rem - h * 56;
    const __half* abase = g_x16 + (size_t)p * CIN;       // + tap/ch at stage time
    const __half* bbase = g_w16 + (size_t)(oc0 + row) * KW;
    uint32_t soff[2];
#pragma unroll
    for (int j = 0; j < 2; j++)
        soff[j] = (uint32_t)row * 128 +
                  ((uint32_t)((q * 2 + j) ^ (row & 7)) << 4);

    // stage s (0..17): tap = s>>1, channel half = s&1
    auto load_stage = [&](int buf, int s) {
        const int tap = s >> 1, ch = s & 1;
        const int rr = tap / 3, ss = tap - rr * 3;
        const int y = h + rr - 1, xx = w + ss - 1;
        const bool ok = ((unsigned)y < 56u) && ((unsigned)xx < 56u);
        const int sz = ok ? 16 : 0;
        const __half* asrc = (ok ? abase + ((rr - 1) * 56 + (ss - 1)) * CIN : abase)
                             + ch * 64;
        const __half* bsrc = bbase + s * 64;
        const uint32_t da = sb + buf * STG_SZ;
        const uint32_t db = da + ASZ;
#pragma unroll
        for (int j = 0; j < 2; j++) {
            CPA16(da + soff[j], asrc + (q * 2 + j) * 8, sz);
            CPA16(db + soff[j], bsrc + (q * 2 + j) * 8, 16);
        }
    };

    float acc[2][4][4];
#pragma unroll
    for (int a = 0; a < 2; a++)
#pragma unroll
        for (int b = 0; b < 4; b++)
#pragma unroll
            for (int c = 0; c < 4; c++) acc[a][b][c] = 0.0f;

    const int lrow = lane & 15;          // row within 16-row tile
    const int lhi  = lane >> 4;          // chunk select for matrices 2,3

    load_stage(0, 0); CPA_COMMIT();
    load_stage(1, 1); CPA_COMMIT();

    for (int s = 0; s < 18; s++) {
        const int buf = s % 3;
        asm volatile("cp.async.wait_group 1;");
        __syncthreads();

        if (s + 2 < 18) load_stage((s + 2) % 3, s + 2);
        CPA_COMMIT();

        const uint32_t As = sb + buf * STG_SZ;
        const uint32_t Bs = As + ASZ;
#pragma unroll
        for (int k = 0; k < 4; k++) {          // k16 steps; 16B chunk = 2k+lhi
            uint32_t bf[4][2];
#pragma unroll
            for (int bt = 0; bt < 2; bt++) {
                int r = warp_n * 32 + bt * 16 + lrow;
                uint32_t addr = Bs + (uint32_t)r * 128 +
                                ((uint32_t)((2 * k + lhi) ^ (r & 7)) << 4);
                ldsm4(bf[bt * 2][0], bf[bt * 2 + 1][0],
                      bf[bt * 2][1], bf[bt * 2 + 1][1], addr);
            }
#pragma unroll
            for (int mt = 0; mt < 2; mt++) {
                int r = warp_m * 32 + mt * 16 + lrow;
                uint32_t addr = As + (uint32_t)r * 128 +
                                ((uint32_t)((2 * k + lhi) ^ (r & 7)) << 4);
                uint32_t a0, a1, a2, a3;
                ldsm4(a0, a1, a2, a3, addr);
#pragma unroll
                for (int nt = 0; nt < 4; nt++) {
                    asm volatile(
                        "mma.sync.aligned.m16n8k16.row.col.f32.f16.f16.f32 "
                        "{%0,%1,%2,%3}, {%4,%5,%6,%7}, {%8,%9}, {%0,%1,%2,%3};\n"
                        : "+f"(acc[mt][nt][0]), "+f"(acc[mt][nt][1]),
                          "+f"(acc[mt][nt][2]), "+f"(acc[mt][nt][3])
                        : "r"(a0), "r"(a1), "r"(a2), "r"(a3),
                          "r"(bf[nt][0]), "r"(bf[nt][1]));
                }
            }
        }
        __syncthreads();
    }

    // ---- epilogue: bias + requant + round + clip, sector-coalesced STG ----
    const int omin = *pmin, omax = *pmax;
    const float fmin = (float)omin, fmax = (float)omax;
    float bj[4][2], sc[4][2];
#pragma unroll
    for (int nt = 0; nt < 4; nt++)
#pragma unroll
        for (int j = 0; j < 2; j++) {
            int oc = oc0 + warp_n * 32 + nt * 8 + tg * 2 + j;
            bj[nt][j] = __ldg(&bias[oc]);
            // A * 2^-N built exactly: N in [16,25) -> normal exponent; single
            // rounding on the multiply == reference's (f*A)/2^N
            float p2 = __int_as_float((127 - __ldg(&Nq[oc])) << 23);
            sc[nt][j] = (float)__ldg(&Aq[oc]) * p2;
        }

#pragma unroll
    for (int mt = 0; mt < 2; mt++) {
#pragma unroll
        for (int hfl = 0; hfl < 2; hfl++) {
            int pix = p0 + warp_m * 32 + mt * 16 + gid + 8 * hfl;
            int n2 = pix / 3136; int rem2 = pix - n2 * 3136;
            float* ob = out + (size_t)n2 * OC * 3136 + rem2;
#pragma unroll
            for (int nt = 0; nt < 4; nt++) {
#pragma unroll
                for (int j = 0; j < 2; j++) {
                    int oc = oc0 + warp_n * 32 + nt * 8 + tg * 2 + j;
                    float f = (acc[mt][nt][hfl * 2 + j] + bj[nt][j]) * sc[nt][j];
                    if (omin >= 0) {
                        f = rintf(f);                    // half-to-even == jnp.round
                        f = fminf(fmaxf(f, fmin), fmax);
                    }
                    ob[(size_t)oc * 3136] = f;
                }
            }
        }
    }
}

// ---------------------------------------------------------------------------
// Launch. Inputs: x, weight_int, bias_int, A, N, out_min, out_max
// ---------------------------------------------------------------------------
extern "C" void kernel_launch(void* const* d_in, const int* in_sizes, int n_in,
                              void* d_out, int out_size) {
    const float* x    = (const float*)d_in[0];
    const float* wt   = (const float*)d_in[1];
    const float* bias = (const float*)d_in[2];
    const int*   Aq   = (const int*)d_in[3];
    const int*   Nq   = (const int*)d_in[4];
    const int*   omin = (const int*)d_in[5];
    const int*   omax = (const int*)d_in[6];
    float* out = (float*)d_out;

    static int configured = 0;
    if (!configured) {
        cudaFuncSetAttribute(qconv, cudaFuncAttributeMaxDynamicSharedMemorySize,
                             SMEM_TOTAL);
        configured = 1;
    }

    prep_fused<<<XBLKS + WBLKS, 256>>>(x, wt);
    dim3 grid(NPIX / 128, OC / 128);
    qconv<<<grid, 512, SMEM_TOTAL>>>(bias, Aq, Nq, omin, omax, out);
}